// round 13
// baseline (speedup 1.0000x reference)
#include <cuda_runtime.h>
#include <cuda_fp16.h>
#include <cstdint>

#define Bv 4
#define Sv 2048
#define Dv 1024
#define Hv 16
#define HDv 64
#define BS 8192            // Bv*Sv

// ---------------- scratch (static device globals; no allocation) -----------
__device__ uint16_t g_W16[4ull * Dv * Dv];                          // fp16 [slot][n][k]
__device__ uint16_t g_Xhi[(size_t)BS * Dv], g_Xlo[(size_t)BS * Dv]; // fp16 [bs][k]
__device__ uint16_t g_Q16[(size_t)BS * Dv];                         // fp16 [bh][s][d], pre-scaled log2e/8
__device__ uint16_t g_K16[(size_t)BS * Dv];                         // fp16 [bh][s][d]
__device__ uint16_t g_V16[(size_t)BS * Dv];                         // fp16 [bh][d][s]
__device__ uint16_t g_Chi[(size_t)BS * Dv], g_Clo[(size_t)BS * Dv]; // fp16 [bs][d]
__device__ uint16_t g_M16[(size_t)Sv * Sv];                         // fp16 mask

// ---------------- helpers ---------------------------------------------------
__device__ __forceinline__ uint32_t sm_u32(const void* p) {
    uint32_t a;
    asm("{ .reg .u64 t; cvta.to.shared.u64 t, %1; cvt.u32.u64 %0, t; }"
        : "=r"(a) : "l"(p));
    return a;
}
__device__ __forceinline__ void hsplit(float x, uint16_t& h, uint16_t& l) {
    __half hh = __float2half_rn(x);
    h = __half_as_ushort(hh);
    l = __half_as_ushort(__float2half_rn(x - __half2float(hh)));
}
__device__ __forceinline__ void split2h(float x, float y, uint32_t& hw, uint32_t& lw) {
    uint16_t hx, lx, hy, ly;
    hsplit(x, hx, lx); hsplit(y, hy, ly);
    hw = (uint32_t)hx | ((uint32_t)hy << 16);
    lw = (uint32_t)lx | ((uint32_t)ly << 16);
}
__device__ __forceinline__ uint32_t pack_half2(float x, float y) {
    __half2 h = __floats2half2_rn(x, y);
    return *(uint32_t*)&h;
}
__device__ __forceinline__ uint32_t h2u(__half2 h) { return *(uint32_t*)&h; }
__device__ __forceinline__ __half2 u2h(uint32_t u) { return *(__half2*)&u; }
__device__ __forceinline__ void mma_f16(float* d, const uint32_t* a, const uint32_t* b) {
    asm volatile(
        "mma.sync.aligned.m16n8k16.row.col.f32.f16.f16.f32 "
        "{%0,%1,%2,%3}, {%4,%5,%6,%7}, {%8,%9}, {%0,%1,%2,%3};"
        : "+f"(d[0]), "+f"(d[1]), "+f"(d[2]), "+f"(d[3])
        : "r"(a[0]), "r"(a[1]), "r"(a[2]), "r"(a[3]), "r"(b[0]), "r"(b[1]));
}
// fp16-accumulator variant: D/C are 2 b32 regs (reg0 = row g pair, reg1 = row g+8)
__device__ __forceinline__ void mma_f16c16(uint32_t* d, const uint32_t* a,
                                           const uint32_t* b) {
    asm volatile(
        "mma.sync.aligned.m16n8k16.row.col.f16.f16.f16.f16 "
        "{%0,%1}, {%2,%3,%4,%5}, {%6,%7}, {%0,%1};"
        : "+r"(d[0]), "+r"(d[1])
        : "r"(a[0]), "r"(a[1]), "r"(a[2]), "r"(a[3]), "r"(b[0]), "r"(b[1]));
}
__device__ __forceinline__ void ldsm4(uint32_t& r0, uint32_t& r1, uint32_t& r2,
                                      uint32_t& r3, uint32_t a) {
    asm volatile("ldmatrix.sync.aligned.m8n8.x4.shared.b16 {%0,%1,%2,%3}, [%4];"
                 : "=r"(r0), "=r"(r1), "=r"(r2), "=r"(r3) : "r"(a));
}
#define EX2F16X2(x) asm("ex2.approx.f16x2 %0, %1;" : "=r"(x) : "r"(x))
#define CP_ASYNC16(dst, src) \
    asm volatile("cp.async.ca.shared.global [%0], [%1], 16;" :: "r"(dst), "l"(src))
#define CP_COMMIT()  asm volatile("cp.async.commit_group;" ::: "memory")
#define CP_WAIT1()   asm volatile("cp.async.wait_group 1;" ::: "memory")

// ---------------- prep kernels ----------------------------------------------
__global__ void __launch_bounds__(256) prep_x(
    const float* __restrict__ X, uint16_t* __restrict__ xh, uint16_t* __restrict__ xl)
{
    size_t i = ((size_t)blockIdx.x * 256 + threadIdx.x) * 4;
    float4 v = *(const float4*)(X + i);
    uint32_t h0, l0, h1, l1;
    split2h(v.x, v.y, h0, l0);
    split2h(v.z, v.w, h1, l1);
    *(uint32_t*)(xh + i) = h0; *(uint32_t*)(xh + i + 2) = h1;
    *(uint32_t*)(xl + i) = l0; *(uint32_t*)(xl + i + 2) = l1;
}

__global__ void __launch_bounds__(256) prep_mask(
    const float* __restrict__ M, uint16_t* __restrict__ m16)
{
    size_t i = ((size_t)blockIdx.x * 256 + threadIdx.x) * 4;
    float4 v = *(const float4*)(M + i);
    *(uint32_t*)(m16 + i)     = pack_half2(v.x, v.y);
    *(uint32_t*)(m16 + i + 2) = pack_half2(v.z, v.w);
}

__global__ void __launch_bounds__(256) prep_w(
    const float* __restrict__ W0, const float* __restrict__ W1,
    const float* __restrict__ W2, const float* __restrict__ W3,
    uint16_t* __restrict__ wo)
{
    __shared__ float t[32][33];
    const float* W = (blockIdx.z == 0) ? W0 : (blockIdx.z == 1) ? W1
                   : (blockIdx.z == 2) ? W2 : W3;
    uint16_t* oh = wo + (size_t)blockIdx.z * Dv * Dv;
    int x = blockIdx.x * 32 + threadIdx.x;
    int y0 = blockIdx.y * 32;
#pragma unroll
    for (int j = threadIdx.y; j < 32; j += 8)
        t[j][threadIdx.x] = W[(size_t)(y0 + j) * Dv + x];
    __syncthreads();
    int ox = blockIdx.y * 32 + threadIdx.x;   // k
    int oy0 = blockIdx.x * 32;                // n
#pragma unroll
    for (int j = threadIdx.y; j < 32; j += 8)
        oh[(size_t)(oy0 + j) * Dv + ox] =
            __half_as_ushort(__float2half_rn(t[threadIdx.x][j]));
}

// ---------------- single-single fp16 GEMM, BK=64 (merged Q+K) ---------------
#define G2PW   36
#define G2ARR  (128 * G2PW)
#define G2BUF  (2 * G2ARR)
#define G2SMEM (2 * G2BUF * 4)    // 73728 bytes

// Q scale: (1/8) * log2(e) — folds 1/sqrt(HD) and the exp2 conversion.
#define QSCALE 0.18033688f

__global__ void __launch_bounds__(256, 2) gemmQK(
    const uint16_t* __restrict__ A0, const uint16_t* __restrict__ Wbase,
    const float* __restrict__ bq, const float* __restrict__ bk,
    uint16_t* __restrict__ oq, uint16_t* __restrict__ ok)
{
    extern __shared__ uint32_t smw[];
    const uint32_t smb = sm_u32(smw);
    const int tid = threadIdx.x;
    const int wid = tid >> 5, lane = tid & 31;
    const int g = lane >> 2, t = lane & 3;
    const int wm = (wid >> 2) * 64, wn = (wid & 3) * 32;
    const int bm = blockIdx.y * 128, bn = blockIdx.x * 128;
    const int slot = blockIdx.z;
    const uint16_t* B0 = Wbase + (size_t)slot * Dv * Dv;
    const float* bias = slot ? bk : bq;
    const float scale = slot ? 1.0f : QSCALE;
    uint16_t* o16 = slot ? ok : oq;

    const int arow = lane & 15, ahalf = (lane >> 4) * 4;
    const int brow = (lane & 7) + ((lane >> 4) << 3), bhalf = ((lane >> 3) & 1) * 4;
    const uint32_t aw0 = (uint32_t)(wm + arow) * G2PW + ahalf;
    const uint32_t bwr = (uint32_t)(wn + brow) * G2PW + bhalf;

    float acc[4][4][4];
#pragma unroll
    for (int mt = 0; mt < 4; mt++)
#pragma unroll
        for (int nt = 0; nt < 4; nt++)
#pragma unroll
            for (int c = 0; c < 4; c++) acc[mt][nt][c] = 0.f;

    auto stage = [&](int ch, int p) {
        const int k0 = ch * 64;
        const uint32_t base = smb + p * G2BUF * 4;
#pragma unroll
        for (int it = 0; it < 4; it++) {
            int idx = tid + it * 256;
            int r = idx >> 3, c = idx & 7;
            uint32_t d = base + (r * G2PW + c * 4) * 4;
            CP_ASYNC16(d,             A0 + (size_t)(bm + r) * Dv + k0 + c * 8);
            CP_ASYNC16(d + G2ARR * 4, B0 + (size_t)(bn + r) * Dv + k0 + c * 8);
        }
    };

    stage(0, 0); CP_COMMIT();
    stage(1, 1); CP_COMMIT();

    for (int ch = 0; ch < 16; ch++) {
        CP_WAIT1();
        __syncthreads();
        const uint32_t pb = smb + ((ch & 1) * G2BUF) * 4;
#pragma unroll
        for (int ks = 0; ks < 4; ks++) {
            const uint32_t kb4 = ks * 8 * 4;
            uint32_t af[4][4], bf[4][2];
#pragma unroll
            for (int mt = 0; mt < 4; mt++) {
                uint32_t ad = pb + (aw0 + mt * 16 * G2PW) * 4 + kb4;
                ldsm4(af[mt][0], af[mt][1], af[mt][2], af[mt][3], ad);
            }
#pragma unroll
            for (int pr = 0; pr < 2; pr++) {
                uint32_t bd = pb + (G2ARR + bwr + pr * 16 * G2PW) * 4 + kb4;
                ldsm4(bf[2 * pr][0], bf[2 * pr][1],
                      bf[2 * pr + 1][0], bf[2 * pr + 1][1], bd);
            }
#pragma unroll
            for (int mt = 0; mt < 4; mt++)
#pragma unroll
                for (int nt = 0; nt < 4; nt++)
                    mma_f16(acc[mt][nt], af[mt], bf[nt]);
        }
        __syncthreads();
        if (ch < 14) {
            stage(ch + 2, ch & 1);
            CP_COMMIT();
        }
    }

    // epilogue: fp16 single, permuted [bh][s][d]
#pragma unroll
    for (int mt = 0; mt < 4; mt++) {
#pragma unroll
        for (int nt = 0; nt < 4; nt++) {
            const int row = bm + wm + mt * 16 + g;
            const int col = bn + wn + nt * 8 + 2 * t;
            float2 bs = *(const float2*)(bias + col);
            float v0x = (acc[mt][nt][0] + bs.x) * scale;
            float v0y = (acc[mt][nt][1] + bs.y) * scale;
            float v1x = (acc[mt][nt][2] + bs.x) * scale;
            float v1y = (acc[mt][nt][3] + bs.y) * scale;
            int bb = row >> 11, ss = row & (Sv - 1);
            int hh = col >> 6, hd = col & (HDv - 1);
            size_t d0 = ((size_t)(bb * Hv + hh) * Sv + ss) * HDv + hd;
            size_t d1 = ((size_t)(bb * Hv + hh) * Sv + ss + 8) * HDv + hd;
            *(uint32_t*)(o16 + d0) = pack_half2(v0x, v0y);
            *(uint32_t*)(o16 + d1) = pack_half2(v1x, v1y);
        }
    }
}

// ---------------- 2-term fp16 GEMM (V and O projections), BK=32 -------------
#define GPW   20
#define GARR  (128 * GPW)
#define GBUFW (3 * GARR)
#define GSMEM_B (2 * GBUFW * 4)  // 61440 bytes

template <int ASPLIT, int MODE>
__global__ void __launch_bounds__(256, 2) gemm2(
    const uint16_t* __restrict__ A0, const uint16_t* __restrict__ A1,
    const uint16_t* __restrict__ B0, const uint16_t* __restrict__ B1,
    const float* __restrict__ bias, float scale,
    float* __restrict__ outf, uint16_t* __restrict__ o16)
{
    extern __shared__ uint32_t smw[];
    const uint32_t smb = sm_u32(smw);
    const int tid = threadIdx.x;
    const int wid = tid >> 5, lane = tid & 31;
    const int g = lane >> 2, t = lane & 3;
    const int wm = (wid >> 2) * 64, wn = (wid & 3) * 32;
    const int bm = blockIdx.y * 128, bn = blockIdx.x * 128;

    const int arow = lane & 15, ahalf = (lane >> 4) * 4;
    const int brow = (lane & 7) + ((lane >> 4) << 3), bhalf = ((lane >> 3) & 1) * 4;
    const uint32_t aw0 = (uint32_t)(wm + arow) * GPW + ahalf;
    const uint32_t bwr = (uint32_t)(wn + brow) * GPW + bhalf;

    float acc[4][4][4];
#pragma unroll
    for (int mt = 0; mt < 4; mt++)
#pragma unroll
        for (int nt = 0; nt < 4; nt++)
#pragma unroll
            for (int c = 0; c < 4; c++) acc[mt][nt][c] = 0.f;

    auto stage = [&](int ch, int p) {
        const int k0 = ch * 32;
        const uint32_t base = smb + p * GBUFW * 4;
#pragma unroll
        for (int it = 0; it < 2; it++) {
            int idx = tid + it * 256;
            int r = idx >> 2, c = idx & 3;
            uint32_t d = base + (r * GPW + c * 4) * 4;
            if (ASPLIT == 1) {
                CP_ASYNC16(d,                A0 + (size_t)(bm + r) * Dv + k0 + c * 8);
                CP_ASYNC16(d + GARR * 4,     A1 + (size_t)(bm + r) * Dv + k0 + c * 8);
                CP_ASYNC16(d + 2 * GARR * 4, B0 + (size_t)(bn + r) * Dv + k0 + c * 8);
            } else {
                CP_ASYNC16(d,                A0 + (size_t)(bm + r) * Dv + k0 + c * 8);
                CP_ASYNC16(d + GARR * 4,     B0 + (size_t)(bn + r) * Dv + k0 + c * 8);
                CP_ASYNC16(d + 2 * GARR * 4, B1 + (size_t)(bn + r) * Dv + k0 + c * 8);
            }
        }
    };

    stage(0, 0); CP_COMMIT();
    stage(1, 1); CP_COMMIT();

    for (int ch = 0; ch < 32; ch++) {
        CP_WAIT1();
        __syncthreads();
        const uint32_t pb = smb + ((ch & 1) * GBUFW) * 4;
#pragma unroll
        for (int ks = 0; ks < 2; ks++) {
            const uint32_t kb4 = ks * 8 * 4;
            if (ASPLIT == 1) {
                uint32_t ah[4][4], al[4][4], bf[4][2];
#pragma unroll
                for (int mt = 0; mt < 4; mt++) {
                    uint32_t ad = pb + (aw0 + mt * 16 * GPW) * 4 + kb4;
                    ldsm4(ah[mt][0], ah[mt][1], ah[mt][2], ah[mt][3], ad);
                    ldsm4(al[mt][0], al[mt][1], al[mt][2], al[mt][3], ad + GARR * 4);
                }
#pragma unroll
                for (int pr = 0; pr < 2; pr++) {
                    uint32_t bd = pb + (2 * GARR + bwr + pr * 16 * GPW) * 4 + kb4;
                    ldsm4(bf[2 * pr][0], bf[2 * pr][1],
                          bf[2 * pr + 1][0], bf[2 * pr + 1][1], bd);
                }
#pragma unroll
                for (int mt = 0; mt < 4; mt++)
#pragma unroll
                    for (int nt = 0; nt < 4; nt++) {
                        mma_f16(acc[mt][nt], ah[mt], bf[nt]);
                        mma_f16(acc[mt][nt], al[mt], bf[nt]);
                    }
            } else {
                uint32_t af[4][4], bh[4][2], bl[4][2];
#pragma unroll
                for (int mt = 0; mt < 4; mt++) {
                    uint32_t ad = pb + (aw0 + mt * 16 * GPW) * 4 + kb4;
                    ldsm4(af[mt][0], af[mt][1], af[mt][2], af[mt][3], ad);
                }
#pragma unroll
                for (int pr = 0; pr < 2; pr++) {
                    uint32_t bd = pb + (GARR + bwr + pr * 16 * GPW) * 4 + kb4;
                    ldsm4(bh[2 * pr][0], bh[2 * pr][1],
                          bh[2 * pr + 1][0], bh[2 * pr + 1][1], bd);
                    ldsm4(bl[2 * pr][0], bl[2 * pr][1],
                          bl[2 * pr + 1][0], bl[2 * pr + 1][1], bd + GARR * 4);
                }
#pragma unroll
                for (int mt = 0; mt < 4; mt++)
#pragma unroll
                    for (int nt = 0; nt < 4; nt++) {
                        mma_f16(acc[mt][nt], af[mt], bh[nt]);
                        mma_f16(acc[mt][nt], af[mt], bl[nt]);
                    }
            }
        }
        __syncthreads();
        if (ch < 30) {
            stage(ch + 2, ch & 1);
            CP_COMMIT();
        }
    }

    // ---- epilogue ----
#pragma unroll
    for (int mt = 0; mt < 4; mt++) {
#pragma unroll
        for (int nt = 0; nt < 4; nt++) {
            const int row = bm + wm + mt * 16 + g;
            const int col = bn + wn + nt * 8 + 2 * t;
            float v0x, v0y, v1x, v1y;
            if (MODE == 2) {
                float b0 = bias[row], b1 = bias[row + 8];
                v0x = acc[mt][nt][0] + b0; v0y = acc[mt][nt][1] + b0;
                v1x = acc[mt][nt][2] + b1; v1y = acc[mt][nt][3] + b1;
            } else {
                float2 bs = *(const float2*)(bias + col);
                v0x = (acc[mt][nt][0] + bs.x) * scale;
                v0y = (acc[mt][nt][1] + bs.y) * scale;
                v1x = (acc[mt][nt][2] + bs.x) * scale;
                v1y = (acc[mt][nt][3] + bs.y) * scale;
            }
            if (MODE == 0) {
                float2 a = {v0x, v0y}, b2 = {v1x, v1y};
                *(float2*)(outf + (size_t)row * Dv + col) = a;
                *(float2*)(outf + (size_t)(row + 8) * Dv + col) = b2;
            } else {  // MODE 2 (V): fp16 single, [bh][d][s]
                int hh = row >> 6, hd = row & (HDv - 1);
                int bb = col >> 11, ss = col & (Sv - 1);
                size_t d0 = ((size_t)(bb * Hv + hh) * HDv + hd) * Sv + ss;
                size_t d1 = ((size_t)(bb * Hv + hh) * HDv + hd + 8) * Sv + ss;
                *(uint32_t*)(o16 + d0) = pack_half2(v0x, v0y);
                *(uint32_t*)(o16 + d1) = pack_half2(v1x, v1y);
            }
        }
    }
}

// ---------------- flash attention: fp16-accum S-MMA, OFF=0 softmax ----------
// Scores accumulate in fp16 directly in P-fragment layout (log2e folded in Q).
// p = exp2(mask * s'): masked entries -> 2^0 = 1 = exp(0), matching the
// reference's multiplicative-mask semantics; softmax ratio unchanged.
// Softmax per half2 pair: one HMUL2 + one EX2. No cvt, no pack, no max.
#define APW   36
#define AQ_W   (128 * APW)
#define AKV_W  (2 * 64 * APW)
#define ASMEM_B ((AQ_W + 2 * AKV_W) * 4)   // 55296 bytes

__global__ void __launch_bounds__(256, 2) attn1(
    const uint16_t* __restrict__ Q16, const uint16_t* __restrict__ K16,
    const uint16_t* __restrict__ V16, const uint16_t* __restrict__ M16,
    uint16_t* __restrict__ Chi, uint16_t* __restrict__ Clo)
{
    extern __shared__ uint32_t smw[];
    const uint32_t smb = sm_u32(smw);
    const int tid = threadIdx.x;
    const int wid = tid >> 5, lane = tid & 31;
    const int g = lane >> 2, t = lane & 3;
    const int b = blockIdx.z, h = blockIdx.y;
    const int q0 = blockIdx.x * 128;
    const int bhh = b * Hv + h;

    const int arow = lane & 15, ahalf = (lane >> 4) * 4;
    const int brow = (lane & 7) + ((lane >> 4) << 3), bhalf = ((lane >> 3) & 1) * 4;
    const uint32_t awQ = (uint32_t)(wid * 16 + arow) * APW + ahalf;
    const uint32_t bw = (uint32_t)brow * APW + bhalf;

    // stage Q (128 rows x 128B)
#pragma unroll
    for (int i = 0; i < 4; i++) {
        int idx = tid + i * 256;
        int r = idx >> 3, c = idx & 7;
        CP_ASYNC16(smb + (r * APW + c * 4) * 4,
                   Q16 + ((size_t)bhh * Sv + q0 + r) * HDv + c * 8);
    }

    auto stageKV = [&](int kv0, int buf) {
        const uint32_t base = AQ_W + buf * AKV_W;
#pragma unroll
        for (int i = 0; i < 2; i++) {
            int idx = tid + i * 256;
            int r = idx >> 3, c = idx & 7;
            uint32_t off = (r * APW + c * 4) * 4;
            CP_ASYNC16(smb + base * 4 + off,
                       K16 + ((size_t)bhh * Sv + kv0 + r) * HDv + c * 8);
            CP_ASYNC16(smb + (base + 64 * APW) * 4 + off,
                       V16 + ((size_t)bhh * HDv + r) * Sv + kv0 + c * 8);
        }
    };

    stageKV(0, 0); CP_COMMIT();
    stageKV(64, 1); CP_COMMIT();

    float l_i[2] = {0.f, 0.f};
    float acc_o[8][4];
#pragma unroll
    for (int nt = 0; nt < 8; nt++)
#pragma unroll
        for (int c = 0; c < 4; c++) acc_o[nt][c] = 0.f;

    const int qrow0 = q0 + wid * 16 + g;

    for (int it = 0; it < Sv / 64; it++) {
        const int kv0 = it * 64, buf = it & 1;
        CP_WAIT1();
        __syncthreads();
        const uint32_t kslot = AQ_W + buf * AKV_W;
        const uint32_t vslot = kslot + 64 * APW;

        // S' = Q @ K^T, fp16 accumulators already in P-fragment layout:
        // sw[nt][0] = row g pair (cols 2t,2t+1), sw[nt][1] = row g+8 pair
        uint32_t sw[8][2];
#pragma unroll
        for (int nt = 0; nt < 8; nt++) { sw[nt][0] = 0u; sw[nt][1] = 0u; }

#pragma unroll
        for (int ks = 0; ks < 4; ks++) {
            const uint32_t kb4 = ks * 8 * 4;
            uint32_t qf[4];
            ldsm4(qf[0], qf[1], qf[2], qf[3], smb + awQ * 4 + kb4);
#pragma unroll
            for (int pr = 0; pr < 4; pr++) {
                uint32_t kd = smb + (kslot + pr * 16 * APW + bw) * 4 + kb4;
                uint32_t kh[2][2];
                ldsm4(kh[0][0], kh[0][1], kh[1][0], kh[1][1], kd);
                mma_f16c16(sw[2 * pr],     qf, kh[0]);
                mma_f16c16(sw[2 * pr + 1], qf, kh[1]);
            }
        }

        // p = exp2(mask * s') — HMUL2 + EX2 per half2 pair, in place
        const uint16_t* mrow0 = M16 + (size_t)qrow0 * Sv + kv0 + 2 * t;
        const uint16_t* mrow1 = mrow0 + 8 * (size_t)Sv;
#pragma unroll
        for (int nt = 0; nt < 8; nt++) {
            sw[nt][0] = h2u(__hmul2(u2h(sw[nt][0]), *(const __half2*)(mrow0 + nt * 8)));
            sw[nt][1] = h2u(__hmul2(u2h(sw[nt][1]), *(const __half2*)(mrow1 + nt * 8)));
            EX2F16X2(sw[nt][0]);
            EX2F16X2(sw[nt][1]);
        }
        // row sums
        float rs0 = 0.f, rs1 = 0.f;
#pragma unroll
        for (int nt = 0; nt < 8; nt += 2) {
            float2 f0 = __half22float2(__hadd2(u2h(sw[nt][0]), u2h(sw[nt + 1][0])));
            float2 f1 = __half22float2(__hadd2(u2h(sw[nt][1]), u2h(sw[nt + 1][1])));
            rs0 += f0.x + f0.y;
            rs1 += f1.x + f1.y;
        }
        l_i[0] += rs0;
        l_i[1] += rs1;

        // O += P @ V — P fragments directly from sw registers
#pragma unroll
        for (int ks = 0; ks < 4; ks++) {
            const uint32_t kb4 = ks * 8 * 4;
            uint32_t pf[4];
            pf[0] = sw[2 * ks][0];
            pf[1] = sw[2 * ks][1];
            pf[2] = sw[2 * ks + 1][0];
            pf[3] = sw[2 * ks + 1][1];
#pragma unroll
            for (int pr = 0; pr < 4; pr++) {
                uint32_t vd = smb + (vslot + pr * 16 * APW + bw) * 4 + kb4;
                uint32_t vh[2][2];
                ldsm4(vh[0][0], vh[0][1], vh[1][0], vh[1][1], vd);
                mma_f16(acc_o[2 * pr],     pf, vh[0]);
                mma_f16(acc_o[2 * pr + 1], pf, vh[1]);
            }
        }
        __syncthreads();
        if (it < Sv / 64 - 2) {
            stageKV(kv0 + 128, buf);
            CP_COMMIT();
        }
    }

    // lane-quad reduce of l (deferred out of the main loop)
    l_i[0] += __shfl_xor_sync(0xffffffffu, l_i[0], 1);
    l_i[0] += __shfl_xor_sync(0xffffffffu, l_i[0], 2);
    l_i[1] += __shfl_xor_sync(0xffffffffu, l_i[1], 1);
    l_i[1] += __shfl_xor_sync(0xffffffffu, l_i[1], 2);

    // finalize: CTX fp16 hi/lo at [(b*Sv + qrow)][h*64 + col]
    float inv0 = 1.f / l_i[0], inv1 = 1.f / l_i[1];
    size_t o0 = ((size_t)(b * Sv + qrow0)) * Dv + h * HDv;
    size_t o1 = o0 + 8 * (size_t)Dv;
#pragma unroll
    for (int nt = 0; nt < 8; nt++) {
        uint32_t hw, lw;
        split2h(acc_o[nt][0] * inv0, acc_o[nt][1] * inv0, hw, lw);
        *(uint32_t*)(Chi + o0 + nt * 8 + 2 * t) = hw;
        *(uint32_t*)(Clo + o0 + nt * 8 + 2 * t) = lw;
        split2h(acc_o[nt][2] * inv1, acc_o[nt][3] * inv1, hw, lw);
        *(uint32_t*)(Chi + o1 + nt * 8 + 2 * t) = hw;
        *(uint32_t*)(Clo + o1 + nt * 8 + 2 * t) = lw;
    }
}

// ---------------------------------------------------------------------------
extern "C" void kernel_launch(void* const* d_in, const int* in_sizes, int n_in,
                              void* d_out, int out_size)
{
    const float* x    = (const float*)d_in[0];
    const float* mask = (const float*)d_in[1];
    const float* Wq = (const float*)d_in[2]; const float* bq = (const float*)d_in[3];
    const float* Wk = (const float*)d_in[4]; const float* bk = (const float*)d_in[5];
    const float* Wv = (const float*)d_in[6]; const float* bv = (const float*)d_in[7];
    const float* Wo = (const float*)d_in[8]; const float* bo = (const float*)d_in[9];

    uint16_t *w16, *xhi, *xlo, *q16, *k16, *v16, *chi, *clo, *m16;
    cudaGetSymbolAddress((void**)&w16, g_W16);
    cudaGetSymbolAddress((void**)&xhi, g_Xhi); cudaGetSymbolAddress((void**)&xlo, g_Xlo);
    cudaGetSymbolAddress((void**)&q16, g_Q16); cudaGetSymbolAddress((void**)&k16, g_K16);
    cudaGetSymbolAddress((void**)&v16, g_V16);
    cudaGetSymbolAddress((void**)&chi, g_Chi); cudaGetSymbolAddress((void**)&clo, g_Clo);
    cudaGetSymbolAddress((void**)&m16, g_M16);

    prep_w<<<dim3(32, 32, 4), dim3(32, 8)>>>(Wq, Wk, Wv, Wo, w16);
    prep_x<<<(BS * Dv) / 1024, 256>>>(x, xhi, xlo);
    prep_mask<<<(Sv * Sv) / 1024, 256>>>(mask, m16);

    cudaFuncSetAttribute(gemmQK,      cudaFuncAttributeMaxDynamicSharedMemorySize, G2SMEM);
    cudaFuncSetAttribute(gemm2<1, 0>, cudaFuncAttributeMaxDynamicSharedMemorySize, GSMEM_B);
    cudaFuncSetAttribute(gemm2<0, 2>, cudaFuncAttributeMaxDynamicSharedMemorySize, GSMEM_B);
    cudaFuncSetAttribute(attn1,       cudaFuncAttributeMaxDynamicSharedMemorySize, ASMEM_B);

    const size_t WSL = (size_t)Dv * Dv;
    dim3 gQK(Dv / 128, BS / 128, 2);  // merged Q + K
    dim3 gStd(Dv / 128, BS / 128);
    dim3 gVt(BS / 128, Dv / 128);

    gemmQK<<<gQK, 256, G2SMEM>>>(xhi, w16, bq, bk, q16, k16);
    gemm2<0, 2><<<gVt, 256, GSMEM_B>>>(w16 + 2 * WSL, nullptr, xhi, xlo,
                                       bv, 1.0f, nullptr, v16);

    attn1<<<dim3(Sv / 128, Hv, Bv), 256, ASMEM_B>>>(q16, k16, v16, m16, chi, clo);

    gemm2<1, 0><<<gStd, 256, GSMEM_B>>>(chi, clo, w16 + 3 * WSL, nullptr,
                                        bo, 1.0f, (float*)d_out, nullptr);
}